// round 4
// baseline (speedup 1.0000x reference)
#include <cuda_runtime.h>

#define BATCH 4
#define NSEQ  4096
#define DIM   64
#define BSTRIDE (NSEQ*DIM)   // 262144 elements per batch slice

// Scratch (allocation-free: __device__ globals)
__device__ float g_q[BATCH*NSEQ*DIM];
__device__ float g_v[BATCH*NSEQ*DIM];
__device__ float g_attn[BATCH*NSEQ*DIM];
__device__ float g_x1[BATCH*NSEQ*DIM];

__device__ __forceinline__ float fsig(float x) {
    return __fdividef(1.f, 1.f + __expf(-x));
}

// ---------------------------------------------------------------------------
// Q/V projection with gather from the [B,H,W,C] tensor.
// mode 0 (height stage): X[n][k] = src[b*BS + k*4096 + n],        n0 = bx*64
// mode 1 (width  stage): X[n][k] = g_x1[b*BS + bx*4096 + k*64 + nn]
// q[n][d] = sum_k X[n][k]*Wq[k][d] + bq[d]   (same for v)
// ---------------------------------------------------------------------------
__global__ __launch_bounds__(256) void qv_kernel(
    const float* __restrict__ src,
    const float* __restrict__ wq, const float* __restrict__ bq,
    const float* __restrict__ wv, const float* __restrict__ bv,
    int mode)
{
    __shared__ float sX[64][64];    // sX[k][n_local]; reads are warp-broadcast
    __shared__ float sWq[64][64];
    __shared__ float sWv[64][64];

    const int b = blockIdx.y, bx = blockIdx.x;
    const int t = threadIdx.x;

    const float* s = (mode == 0) ? src : (const float*)g_x1;
    const long base = (long)b*BSTRIDE + (mode == 0 ? bx*64 : bx*4096);
    const int strideK = (mode == 0) ? 4096 : 64;

    // Load X tile: 64 k-rows x 64 n, coalesced float4
    for (int i = t; i < 64*16; i += 256) {
        int k = i >> 4, n4 = (i & 15) * 4;
        float4 val = *reinterpret_cast<const float4*>(s + base + (long)k*strideK + n4);
        *reinterpret_cast<float4*>(&sX[k][n4]) = val;
    }
    for (int i = t; i < 4096; i += 256) {
        sWq[i>>6][i&63] = wq[i];
        sWv[i>>6][i&63] = wv[i];
    }
    __syncthreads();

    const int d = t & 63, g = t >> 6;   // thread owns column d, rows g+4i
    float aq[16], av[16];
    #pragma unroll
    for (int i = 0; i < 16; i++) { aq[i] = 0.f; av[i] = 0.f; }

    #pragma unroll 8
    for (int k = 0; k < 64; k++) {
        float wqv = sWq[k][d], wvv = sWv[k][d];
        #pragma unroll
        for (int i = 0; i < 16; i++) {
            float xv = sX[k][g + 4*i];   // broadcast across the 64 d-threads
            aq[i] += xv * wqv;
            av[i] += xv * wvv;
        }
    }

    const float bqd = bq[d], bvd = bv[d];
    const int n0 = bx * 64;
    #pragma unroll
    for (int i = 0; i < 16; i++) {
        int row = n0 + g + 4*i;
        g_q[b*BSTRIDE + row*64 + d] = aq[i] + bqd;
        g_v[b*BSTRIDE + row*64 + d] = av[i] + bvd;
    }
}

// ---------------------------------------------------------------------------
// Fused sigmoid-attention: out[n][d] = sum_m sigmoid(q[n].q[m]/8) * v[m][d]
// 128 threads, TN=TM=64. Per-thread: 4 rows (sr+16i) x 8 cols (sc+8j).
// Pitches chosen for conflict-free/broadcast LDS in both phases.
// ---------------------------------------------------------------------------
#define APITCH 68
#define SPITCH 72
#define ATTN_SMEM ((3*64*APITCH + 64*SPITCH) * 4)   // 70656 bytes

__global__ __launch_bounds__(128) void attn_kernel()
{
    extern __shared__ float sm[];
    float* sQn = sm;
    float* sQm = sm + 64*APITCH;
    float* sVm = sm + 2*64*APITCH;
    float* sS  = sm + 3*64*APITCH;

    const int b  = blockIdx.y;
    const int n0 = blockIdx.x * 64;
    const float* qb = g_q + b*BSTRIDE;
    const float* vb = g_v + b*BSTRIDE;
    const int t  = threadIdx.x;
    const int sr = t >> 3;   // 0..15 (row group)
    const int sc = t & 7;    // 0..7  (col group)

    // Load Qn tile once
    for (int i = t; i < 1024; i += 128) {
        int row = i >> 4, c4 = (i & 15) * 4;
        *reinterpret_cast<float4*>(&sQn[row*APITCH + c4]) =
            *reinterpret_cast<const float4*>(qb + (n0 + row)*64 + c4);
    }

    float acc[4][8];
    #pragma unroll
    for (int i = 0; i < 4; i++)
        #pragma unroll
        for (int j = 0; j < 8; j++) acc[i][j] = 0.f;

    for (int m0 = 0; m0 < NSEQ; m0 += 64) {
        __syncthreads();   // previous tile's consumers done
        for (int i = t; i < 1024; i += 128) {
            int row = i >> 4, c4 = (i & 15) * 4;
            *reinterpret_cast<float4*>(&sQm[row*APITCH + c4]) =
                *reinterpret_cast<const float4*>(qb + (m0 + row)*64 + c4);
            *reinterpret_cast<float4*>(&sVm[row*APITCH + c4]) =
                *reinterpret_cast<const float4*>(vb + (m0 + row)*64 + c4);
        }
        __syncthreads();

        // --- S = Qn . Qm^T (4x8 register tile per thread) ---
        float sreg[4][8];
        #pragma unroll
        for (int i = 0; i < 4; i++)
            #pragma unroll
            for (int j = 0; j < 8; j++) sreg[i][j] = 0.f;

        #pragma unroll 8
        for (int k = 0; k < 64; k++) {
            float a[4], bb[8];
            #pragma unroll
            for (int i = 0; i < 4; i++) a[i]  = sQn[(sr + 16*i)*APITCH + k];
            #pragma unroll
            for (int j = 0; j < 8; j++) bb[j] = sQm[(sc + 8*j)*APITCH + k];
            #pragma unroll
            for (int i = 0; i < 4; i++)
                #pragma unroll
                for (int j = 0; j < 8; j++) sreg[i][j] += a[i] * bb[j];
        }

        // sigmoid(S/8) -> smem
        #pragma unroll
        for (int i = 0; i < 4; i++)
            #pragma unroll
            for (int j = 0; j < 8; j++)
                sS[(sr + 16*i)*SPITCH + sc + 8*j] = fsig(sreg[i][j] * 0.125f);
        __syncthreads();

        // --- acc += S . Vm ---
        #pragma unroll 4
        for (int m = 0; m < 64; m++) {
            float ss[4], vv[8];
            #pragma unroll
            for (int i = 0; i < 4; i++) ss[i] = sS[(sr + 16*i)*SPITCH + m];
            #pragma unroll
            for (int j = 0; j < 8; j++) vv[j] = sVm[m*APITCH + sc + 8*j];
            #pragma unroll
            for (int i = 0; i < 4; i++)
                #pragma unroll
                for (int j = 0; j < 8; j++) acc[i][j] += ss[i] * vv[j];
        }
    }

    float* ob = g_attn + b*BSTRIDE;
    #pragma unroll
    for (int i = 0; i < 4; i++)
        #pragma unroll
        for (int j = 0; j < 8; j++)
            ob[(n0 + sr + 16*i)*64 + sc + 8*j] = acc[i][j];
}

// ---------------------------------------------------------------------------
// x1[b, d*4096 + n] = feature[...] + h_gate * attn_h[b, n, d]
// (transpose through smem so both read and write are coalesced)
// ---------------------------------------------------------------------------
__global__ __launch_bounds__(256) void combine_h_kernel(
    const float* __restrict__ feature, const float* __restrict__ h_gate)
{
    __shared__ float s[64][65];
    const int b = blockIdx.y, n0 = blockIdx.x * 64;
    const int t = threadIdx.x;
    const float* ab = g_attn + b*BSTRIDE;

    for (int i = t; i < 4096; i += 256) {
        int row = i >> 6, col = i & 63;
        s[row][col] = ab[(n0 + row)*64 + col];
    }
    __syncthreads();
    const float hg = h_gate[0];
    const float* fb = feature + b*BSTRIDE;
    float* xb = g_x1 + b*BSTRIDE;
    for (int i = t; i < 4096; i += 256) {
        int d = i >> 6, nn = i & 63;
        int idx = d*4096 + n0 + nn;
        xb[idx] = fb[idx] + hg * s[nn][d];
    }
}

// ---------------------------------------------------------------------------
// Final epilogue:
//   feat = feature + x1 + w_gate * attn_w    (attn_w gathered via transpose)
//   p[b,h,w] = conv_b + sum_nc (1 - sigmoid(predict)) * conv_w[nc]
//   out = p * feat
// ---------------------------------------------------------------------------
__global__ __launch_bounds__(256) void final_kernel(
    const float* __restrict__ feature, const float* __restrict__ predict,
    const float* __restrict__ w_gate,
    const float* __restrict__ conv_w, const float* __restrict__ conv_b,
    float* __restrict__ out)
{
    __shared__ float s[64][65];   // s[c][w] = attn_w[b, n=h*64+c, d=w]
    __shared__ float sp[64];
    const int b = blockIdx.y, h = blockIdx.x;
    const int t = threadIdx.x;
    const float* ab = g_attn + b*BSTRIDE + h*4096;

    for (int i = t; i < 4096; i += 256)
        s[i >> 6][i & 63] = ab[i];    // flat = c*64 + w

    if (t < 64) {
        int w = t;
        float acc = conv_b[0];
        const float* pp = predict + (((b*64 + h)*64 + w) * 19);
        #pragma unroll
        for (int nc = 0; nc < 19; nc++)
            acc += (1.f - fsig(pp[nc])) * conv_w[nc];
        sp[w] = acc;
    }
    __syncthreads();

    const float wg = w_gate[0];
    const int base = b*BSTRIDE + h*4096;
    for (int i = t; i < 4096; i += 256) {
        int w = i >> 6, c = i & 63;
        int idx = base + i;           // = b*BS + (h*64+w)*64 + c
        float feat = feature[idx] + g_x1[idx] + wg * s[c][w];
        out[idx] = sp[w] * feat;
    }
}

// ---------------------------------------------------------------------------
extern "C" void kernel_launch(void* const* d_in, const int* in_sizes, int n_in,
                              void* d_out, int out_size)
{
    const float* feature = (const float*)d_in[0];
    const float* predict = (const float*)d_in[1];
    const float* hq_w    = (const float*)d_in[2];
    const float* hq_b    = (const float*)d_in[3];
    const float* hv_w    = (const float*)d_in[4];
    const float* hv_b    = (const float*)d_in[5];
    const float* wq_w    = (const float*)d_in[6];
    const float* wq_b    = (const float*)d_in[7];
    const float* wv_w    = (const float*)d_in[8];
    const float* wv_b    = (const float*)d_in[9];
    const float* h_gate  = (const float*)d_in[10];
    const float* w_gate  = (const float*)d_in[11];
    const float* conv_w  = (const float*)d_in[12];
    const float* conv_b  = (const float*)d_in[13];
    float* out = (float*)d_out;

    // >48KB dynamic smem opt-in (idempotent; first call happens outside capture)
    cudaFuncSetAttribute(attn_kernel,
                         cudaFuncAttributeMaxDynamicSharedMemorySize, ATTN_SMEM);

    dim3 grid(64, BATCH);

    // Stage A: height attention (seq = W*C, dim = H)
    qv_kernel<<<grid, 256>>>(feature, hq_w, hq_b, hv_w, hv_b, 0);
    attn_kernel<<<grid, 128, ATTN_SMEM>>>();
    combine_h_kernel<<<grid, 256>>>(feature, h_gate);

    // Stage B: width attention (seq = H*C, dim = W) on x1
    qv_kernel<<<grid, 256>>>(feature /*unused in mode 1*/, wq_w, wq_b, wv_w, wv_b, 1);
    attn_kernel<<<grid, 128, ATTN_SMEM>>>();

    // Epilogue: feat = feature + x1 + wg*attn_w ; out = p * feat
    final_kernel<<<grid, 256>>>(feature, predict, w_gate, conv_w, conv_b, out);
}

// round 5
// speedup vs baseline: 1.0293x; 1.0293x over previous
#include <cuda_runtime.h>

#define BATCH 4
#define NSEQ  4096
#define DIM   64
#define BSTRIDE (NSEQ*DIM)   // 262144 elements per batch slice

typedef unsigned long long ull;

// Scratch (allocation-free: __device__ globals)
__device__ float g_q[BATCH*NSEQ*DIM];
__device__ float g_v[BATCH*NSEQ*DIM];
__device__ float g_attn[BATCH*NSEQ*DIM];
__device__ float g_x1[BATCH*NSEQ*DIM];

__device__ __forceinline__ float fsig(float x) {
    return __fdividef(1.f, 1.f + __expf(-x));
}

// Packed f32x2 helpers (Blackwell sm_103a)
__device__ __forceinline__ void fma2(ull& d, ull a, ull b) {
    asm("fma.rn.f32x2 %0, %1, %2, %0;" : "+l"(d) : "l"(a), "l"(b));
}
__device__ __forceinline__ ull splat2(float x) {
    ull r; asm("mov.b64 %0, {%1, %1};" : "=l"(r) : "f"(x)); return r;
}
__device__ __forceinline__ float2 unpack2(ull v) {
    float2 f; asm("mov.b64 {%0, %1}, %2;" : "=f"(f.x), "=f"(f.y) : "l"(v)); return f;
}

// ---------------------------------------------------------------------------
// Q/V projection with gather from the [B,H,W,C] tensor.
// mode 0 (height stage): X[n][k] = src[b*BS + k*4096 + n],  n0 = bx*64
// mode 1 (width  stage): X[n][k] = g_x1[b*BS + bx*4096 + k*64 + nn]
// ---------------------------------------------------------------------------
__global__ __launch_bounds__(256) void qv_kernel(
    const float* __restrict__ src,
    const float* __restrict__ wq, const float* __restrict__ bq,
    const float* __restrict__ wv, const float* __restrict__ bv,
    int mode)
{
    __shared__ float sX[64][64];
    __shared__ float sWq[64][64];
    __shared__ float sWv[64][64];

    const int b = blockIdx.y, bx = blockIdx.x;
    const int t = threadIdx.x;

    const float* s = (mode == 0) ? src : (const float*)g_x1;
    const long base = (long)b*BSTRIDE + (mode == 0 ? bx*64 : bx*4096);
    const int strideK = (mode == 0) ? 4096 : 64;

    for (int i = t; i < 64*16; i += 256) {
        int k = i >> 4, n4 = (i & 15) * 4;
        float4 val = *reinterpret_cast<const float4*>(s + base + (long)k*strideK + n4);
        *reinterpret_cast<float4*>(&sX[k][n4]) = val;
    }
    for (int i = t; i < 4096; i += 256) {
        sWq[i>>6][i&63] = wq[i];
        sWv[i>>6][i&63] = wv[i];
    }
    __syncthreads();

    const int d = t & 63, g = t >> 6;
    float aq[16], av[16];
    #pragma unroll
    for (int i = 0; i < 16; i++) { aq[i] = 0.f; av[i] = 0.f; }

    #pragma unroll 8
    for (int k = 0; k < 64; k++) {
        float wqv = sWq[k][d], wvv = sWv[k][d];
        #pragma unroll
        for (int i = 0; i < 16; i++) {
            float xv = sX[k][g + 4*i];
            aq[i] += xv * wqv;
            av[i] += xv * wvv;
        }
    }

    const float bqd = bq[d], bvd = bv[d];
    const int n0 = bx * 64;
    #pragma unroll
    for (int i = 0; i < 16; i++) {
        int row = n0 + g + 4*i;
        g_q[b*BSTRIDE + row*64 + d] = aq[i] + bqd;
        g_v[b*BSTRIDE + row*64 + d] = av[i] + bvd;
    }
}

// ---------------------------------------------------------------------------
// Fused sigmoid-attention, f32x2 packed math.
// CTA tile: TN=128 n-rows x full m-loop, TM=64 m-tile. 128 threads.
// Thread (rg = t>>3 in 0..15, sc = t&7):
//   phase1: rows rg*8 + (2p+e), p<4, e<2 (f32x2 pair along rows)
//           cols sc + 8j, j<8 (scalar Qm + splat)
//   phase2: rows rg*8 + i, i<8 (scalar S + splat)
//           cols 16j + 2sc + e, j<4 (f32x2 pair along cols, native u64 V loads)
// Pitches: sQnT 130, sQm/sVm 68, sS 65 -> all inner accesses conflict-free.
// ---------------------------------------------------------------------------
#define TPITCH 130
#define APITCH 68
#define SPITCH 65
#define ATTN_SMEM ((64*TPITCH + 2*64*APITCH + 128*SPITCH) * 4)   // 101376 B

__global__ __launch_bounds__(128, 1) void attn_kernel()
{
    extern __shared__ float sm[];
    float* sQnT = sm;                       // [64 k][TPITCH] transposed Qn
    float* sQm  = sm + 64*TPITCH;           // [64 m][APITCH]
    float* sVm  = sQm + 64*APITCH;          // [64 m][APITCH]
    float* sS   = sVm + 64*APITCH;          // [128 n][SPITCH]

    const int b  = blockIdx.y;
    const int n0 = blockIdx.x * 128;
    const float* qb = g_q + b*BSTRIDE;
    const float* vb = g_v + b*BSTRIDE;
    const int t  = threadIdx.x;
    const int rg = t >> 3;    // 0..15
    const int sc = t & 7;     // 0..7

    // Transpose Qn tile into sQnT[k][n] (once per CTA)
    for (int i = t; i < 128*16; i += 128) {
        int row = i >> 4, k4 = (i & 15) * 4;
        float4 v = *reinterpret_cast<const float4*>(qb + (n0 + row)*64 + k4);
        sQnT[(k4+0)*TPITCH + row] = v.x;
        sQnT[(k4+1)*TPITCH + row] = v.y;
        sQnT[(k4+2)*TPITCH + row] = v.z;
        sQnT[(k4+3)*TPITCH + row] = v.w;
    }

    ull acc[8][4];
    #pragma unroll
    for (int i = 0; i < 8; i++)
        #pragma unroll
        for (int j = 0; j < 4; j++) acc[i][j] = 0ull;

    for (int m0 = 0; m0 < NSEQ; m0 += 64) {
        __syncthreads();    // prev tile fully consumed (also covers sQnT fill)
        for (int i = t; i < 1024; i += 128) {
            int row = i >> 4, c4 = (i & 15) * 4;
            *reinterpret_cast<float4*>(sQm + row*APITCH + c4) =
                *reinterpret_cast<const float4*>(qb + (m0 + row)*64 + c4);
            *reinterpret_cast<float4*>(sVm + row*APITCH + c4) =
                *reinterpret_cast<const float4*>(vb + (m0 + row)*64 + c4);
        }
        __syncthreads();

        // --- phase 1: S = Qn . Qm^T, pairs along n ---
        ull s2[4][8];
        #pragma unroll
        for (int p = 0; p < 4; p++)
            #pragma unroll
            for (int j = 0; j < 8; j++) s2[p][j] = 0ull;

        #pragma unroll 4
        for (int k = 0; k < 64; k++) {
            ull a[4], bs[8];
            #pragma unroll
            for (int p = 0; p < 4; p++)
                a[p] = *reinterpret_cast<const ull*>(sQnT + k*TPITCH + rg*8 + 2*p);
            #pragma unroll
            for (int j = 0; j < 8; j++)
                bs[j] = splat2(sQm[(sc + 8*j)*APITCH + k]);
            #pragma unroll
            for (int p = 0; p < 4; p++)
                #pragma unroll
                for (int j = 0; j < 8; j++)
                    fma2(s2[p][j], a[p], bs[j]);
        }

        // sigmoid(S/8) -> sS
        #pragma unroll
        for (int p = 0; p < 4; p++)
            #pragma unroll
            for (int j = 0; j < 8; j++) {
                float2 f = unpack2(s2[p][j]);
                sS[(rg*8 + 2*p    )*SPITCH + sc + 8*j] = fsig(f.x * 0.125f);
                sS[(rg*8 + 2*p + 1)*SPITCH + sc + 8*j] = fsig(f.y * 0.125f);
            }
        __syncthreads();

        // --- phase 2: acc += S . Vm, pairs along d ---
        #pragma unroll 4
        for (int m = 0; m < 64; m++) {
            ull vv[4], ssp[8];
            #pragma unroll
            for (int j = 0; j < 4; j++)
                vv[j] = *reinterpret_cast<const ull*>(sVm + m*APITCH + 16*j + 2*sc);
            #pragma unroll
            for (int i = 0; i < 8; i++)
                ssp[i] = splat2(sS[(rg*8 + i)*SPITCH + m]);
            #pragma unroll
            for (int i = 0; i < 8; i++)
                #pragma unroll
                for (int j = 0; j < 4; j++)
                    fma2(acc[i][j], ssp[i], vv[j]);
        }
    }

    float* ob = g_attn + b*BSTRIDE;
    #pragma unroll
    for (int i = 0; i < 8; i++)
        #pragma unroll
        for (int j = 0; j < 4; j++) {
            float2 f = unpack2(acc[i][j]);
            *reinterpret_cast<float2*>(ob + (n0 + rg*8 + i)*64 + 16*j + 2*sc) = f;
        }
}

// ---------------------------------------------------------------------------
// x1[b, d*4096 + n] = feature[...] + h_gate * attn_h[b, n, d]
// ---------------------------------------------------------------------------
__global__ __launch_bounds__(256) void combine_h_kernel(
    const float* __restrict__ feature, const float* __restrict__ h_gate)
{
    __shared__ float s[64][65];
    const int b = blockIdx.y, n0 = blockIdx.x * 64;
    const int t = threadIdx.x;
    const float* ab = g_attn + b*BSTRIDE;

    for (int i = t; i < 4096; i += 256) {
        int row = i >> 6, col = i & 63;
        s[row][col] = ab[(n0 + row)*64 + col];
    }
    __syncthreads();
    const float hg = h_gate[0];
    const float* fb = feature + b*BSTRIDE;
    float* xb = g_x1 + b*BSTRIDE;
    for (int i = t; i < 4096; i += 256) {
        int d = i >> 6, nn = i & 63;
        int idx = d*4096 + n0 + nn;
        xb[idx] = fb[idx] + hg * s[nn][d];
    }
}

// ---------------------------------------------------------------------------
// Final epilogue:
//   feat = feature + x1 + w_gate * attn_w ; p = conv(1-sigmoid(predict)) ; out = p*feat
// ---------------------------------------------------------------------------
__global__ __launch_bounds__(256) void final_kernel(
    const float* __restrict__ feature, const float* __restrict__ predict,
    const float* __restrict__ w_gate,
    const float* __restrict__ conv_w, const float* __restrict__ conv_b,
    float* __restrict__ out)
{
    __shared__ float s[64][65];
    __shared__ float sp[64];
    const int b = blockIdx.y, h = blockIdx.x;
    const int t = threadIdx.x;
    const float* ab = g_attn + b*BSTRIDE + h*4096;

    for (int i = t; i < 4096; i += 256)
        s[i >> 6][i & 63] = ab[i];

    if (t < 64) {
        int w = t;
        float acc = conv_b[0];
        const float* pp = predict + (((b*64 + h)*64 + w) * 19);
        #pragma unroll
        for (int nc = 0; nc < 19; nc++)
            acc += (1.f - fsig(pp[nc])) * conv_w[nc];
        sp[w] = acc;
    }
    __syncthreads();

    const float wg = w_gate[0];
    const int base = b*BSTRIDE + h*4096;
    for (int i = t; i < 4096; i += 256) {
        int w = i >> 6, c = i & 63;
        int idx = base + i;
        float feat = feature[idx] + g_x1[idx] + wg * s[c][w];
        out[idx] = sp[w] * feat;
    }
}

// ---------------------------------------------------------------------------
extern "C" void kernel_launch(void* const* d_in, const int* in_sizes, int n_in,
                              void* d_out, int out_size)
{
    const float* feature = (const float*)d_in[0];
    const float* predict = (const float*)d_in[1];
    const float* hq_w    = (const float*)d_in[2];
    const float* hq_b    = (const float*)d_in[3];
    const float* hv_w    = (const float*)d_in[4];
    const float* hv_b    = (const float*)d_in[5];
    const float* wq_w    = (const float*)d_in[6];
    const float* wq_b    = (const float*)d_in[7];
    const float* wv_w    = (const float*)d_in[8];
    const float* wv_b    = (const float*)d_in[9];
    const float* h_gate  = (const float*)d_in[10];
    const float* w_gate  = (const float*)d_in[11];
    const float* conv_w  = (const float*)d_in[12];
    const float* conv_b  = (const float*)d_in[13];
    float* out = (float*)d_out;

    cudaFuncSetAttribute(attn_kernel,
                         cudaFuncAttributeMaxDynamicSharedMemorySize, ATTN_SMEM);

    dim3 gridQV(64, BATCH);
    dim3 gridAT(NSEQ/128, BATCH);

    // Stage A: height attention (seq = W*C, dim = H)
    qv_kernel<<<gridQV, 256>>>(feature, hq_w, hq_b, hv_w, hv_b, 0);
    attn_kernel<<<gridAT, 128, ATTN_SMEM>>>();
    combine_h_kernel<<<gridQV, 256>>>(feature, h_gate);

    // Stage B: width attention (seq = H*C, dim = W) on x1
    qv_kernel<<<gridQV, 256>>>(feature /*unused in mode 1*/, wq_w, wq_b, wv_w, wv_b, 1);
    attn_kernel<<<gridAT, 128, ATTN_SMEM>>>();

    // Epilogue
    final_kernel<<<gridQV, 256>>>(feature, predict, w_gate, conv_w, conv_b, out);
}